// round 3
// baseline (speedup 1.0000x reference)
#include <cuda_runtime.h>
#include <stdint.h>

#define TT 32
#define NB 4
#define FRAMES (TT*NB)   // frame index tn = t*NB + n

#define C0 128
#define H0 16
#define W0 16
#define C1 64
#define H1 31
#define W1 31
#define C2 32
#define H2 61
#define W2 61
#define C3 2
#define H3 121
#define W3 121

// ---- device scratch ----
__device__ uint8_t  g_cnt0[FRAMES*H0*W0*4];
__device__ uint8_t  g_lst0[FRAMES*H0*W0*4*32];
__device__ float    g_w1r[9*C0*C1];                    // [tap][ci][co], pre-scaled x2
__device__ float    g_w2r[9*C1*C2];
__device__ float    g_w3r[9*C2*C3];
__device__ float    g_z1[(size_t)FRAMES*H1*W1*C1];
__device__ uint8_t  g_cnt1[FRAMES*H1*W1*2];
__device__ uint8_t  g_lst1[FRAMES*H1*W1*2*32];
__device__ float    g_z2[(size_t)FRAMES*H2*W2*C2];
__device__ uint8_t  g_cnt2[FRAMES*H2*W2];
__device__ uint8_t  g_lst2[(size_t)FRAMES*H2*W2*32];
__device__ float    g_z3[(size_t)FRAMES*H3*W3*C3];
__device__ int      g_cnt[3];

// ---- build layer-0 spike lists from input; zero spike counters ----
// warp per (n, pix, word): lane = ci within word; loads 32 t's coalesced.
__global__ void k_list0(const float* __restrict__ x) {
    const int lane = threadIdx.x & 31;
    const int gw = blockIdx.x*(blockDim.x>>5) + (threadIdx.x>>5);
    if (gw == 0 && lane < 3) g_cnt[lane] = 0;
    const int total = NB*H0*W0*4;
    if (gw >= total) return;
    const int word = gw & 3;
    const int pix  = (gw >> 2) % (H0*W0);
    const int n    = gw / (4*H0*W0);
    const int ci = word*32 + lane;
    const float4* xp = (const float4*)(x + (((size_t)n*C0 + ci)*(H0*W0) + pix)*TT);
    float4 v[8];
    #pragma unroll
    for (int q = 0; q < 8; q++) v[q] = xp[q];
    const uint32_t ltmask = (1u << lane) - 1u;
    #pragma unroll
    for (int t = 0; t < TT; t++) {
        float4 vv = v[t >> 2];
        float f = (t&3)==0 ? vv.x : (t&3)==1 ? vv.y : (t&3)==2 ? vv.z : vv.w;
        bool s = (f >= 0.5f);
        uint32_t bal = __ballot_sync(0xffffffffu, s);
        size_t li = ((size_t)(t*NB+n)*(H0*W0) + pix)*4 + word;
        if (s) g_lst0[li*32 + __popc(bal & ltmask)] = (uint8_t)lane;
        if (lane == 0) g_cnt0[li] = (uint8_t)__popc(bal);
    }
}

// ---- rearrange weights: wr[tap][ci][co] = 2 * w[ci][co][tap] ----
__global__ void k_wprep(const float* __restrict__ w, float* __restrict__ wr,
                        int cin, int cout) {
    int idx = blockIdx.x*blockDim.x + threadIdx.x;
    int total = cin*cout*9;
    if (idx >= total) return;
    int tap = idx % 9;
    int rest = idx/9;
    int co = rest % cout;
    int ci = rest / cout;
    wr[(tap*cin + ci)*cout + co] = 2.0f * w[(ci*cout + co)*9 + tap];
}

// ---- parity-specialized sparse transposed conv (gather, list-driven) ----
// PH/PW: output row/col parity. Taps compile-time. Lane = cout within 32-slice
// (slice via blockIdx.y). Order: kh asc, kw asc, word asc, bit asc — single acc.
template<int CIN, int COUT, int HIN, int WIN, int PH, int PW>
__global__ void __launch_bounds__(256)
k_convp(const uint8_t* __restrict__ cnts, const uint8_t* __restrict__ lst,
        const float* __restrict__ wr, float* __restrict__ zOut) {
    constexpr int WORDS = CIN/32;
    constexpr int HOUT = 2*HIN-1, WOUT = 2*WIN-1;
    constexpr int ROWS = PH ? HIN-1 : HIN;
    constexpr int COLS = PW ? WIN-1 : WIN;
    constexpr int NKH = PH ? 2 : 1;
    constexpr int NKW = PW ? 2 : 1;
    constexpr int NT = NKH*NKW;
    extern __shared__ float sW[];    // [NT][CIN][32]
    const int coBase = blockIdx.y << 5;
    for (int i = threadIdx.x; i < NT*CIN*32; i += 256) {
        int ti = i / (CIN*32);
        int r  = i - ti*(CIN*32);
        int ci = r >> 5, c = r & 31;
        int kh = PH ? (ti/NKW)*2 : 1;
        int kw = PW ? (ti%NKW)*2 : 1;
        sW[i] = wr[((kh*3+kw)*CIN + ci)*COUT + coBase + c];
    }
    __syncthreads();
    const int lane = threadIdx.x & 31;
    const int gw = blockIdx.x*8 + (threadIdx.x>>5);
    const int total = FRAMES*ROWS*COLS;
    if (gw >= total) return;
    const int ocol = gw % COLS;
    const int orow = (gw / COLS) % ROWS;
    const int tn   = gw / (COLS*ROWS);
    float acc = 0.f;
    #pragma unroll
    for (int th = 0; th < NKH; th++) {
        const int ih = PH ? (th == 0 ? orow+1 : orow) : orow;
        #pragma unroll
        for (int tw = 0; tw < NKW; tw++) {
            const int iw = PW ? (tw == 0 ? ocol+1 : ocol) : ocol;
            const int ti = th*NKW + tw;
            const size_t pbase = ((size_t)tn*(HIN*WIN) + ih*WIN + iw)*WORDS;
            #pragma unroll
            for (int wo = 0; wo < WORDS; wo++) {
                const int cnt = cnts[pbase + wo];
                const uint8_t* lp = lst + (pbase + wo)*32;
                const float* wb = sW + ((ti*WORDS + wo)*32)*32 + lane;
                int j = 0;
                for (; j + 4 <= cnt; j += 4) {
                    uint32_t q = *(const uint32_t*)(lp + j);
                    acc += wb[((q      ) & 0xFF)*32];
                    acc += wb[((q >>  8) & 0xFF)*32];
                    acc += wb[((q >> 16) & 0xFF)*32];
                    acc += wb[((q >> 24)       )*32];
                }
                for (; j < cnt; j++) acc += wb[lp[j]*32];
            }
        }
    }
    const int oh = PH ? 2*orow+1 : 2*orow;
    const int ow = PW ? 2*ocol+1 : 2*ocol;
    zOut[(((size_t)tn*HOUT + oh)*WOUT + ow)*COUT + coBase + lane] = acc;
}

// ---- CUBA LIF scan; emits next-layer spike lists + counts + spike total ----
template<int C, int HIN, int WIN, int LAYER>
__global__ void k_lifB(const float* __restrict__ z, uint8_t* __restrict__ cnts,
                       uint8_t* __restrict__ lst) {
    constexpr int HOUT = 2*HIN-1, WOUT = 2*WIN-1, POUT = HOUT*WOUT;
    const int idx = blockIdx.x*blockDim.x + threadIdx.x;
    const int total = NB*POUT*C;    // divisible by 32 -> warps fully in/out
    if (idx >= total) return;
    const int c   = idx % C;
    const int pix = (idx / C) % POUT;
    const int n   = idx / (C*POUT);
    const int lane = threadIdx.x & 31;
    const int word = c >> 5;
    const size_t zbase    = ((size_t)n*POUT + pix)*C + c;
    const size_t ztstride = (size_t)NB*POUT*C;
    const size_t lbase    = ((size_t)n*POUT + pix)*(C/32) + word;
    const size_t lstride  = (size_t)NB*POUT*(C/32);
    const uint32_t ltmask = (1u << lane) - 1u;
    float cur = 0.f, vol = 0.f;
    int cnt = 0;
    #pragma unroll
    for (int t = 0; t < TT; t++) {
        float zv = z[(size_t)t*ztstride + zbase];
        cur = 0.5f*cur + zv;
        vol = 0.5f*vol + cur;
        bool s = (vol >= 1.0f);
        vol = s ? 0.f : vol;
        cnt += s ? 1 : 0;
        uint32_t bal = __ballot_sync(0xffffffffu, s);
        size_t li = (size_t)t*lstride + lbase;
        if (s) lst[li*32 + __popc(bal & ltmask)] = (uint8_t)lane;
        if (lane == 0) cnts[li] = (uint8_t)__popc(bal);
    }
    cnt = __reduce_add_sync(0xffffffffu, cnt);
    if (lane == 0) atomicAdd(&g_cnt[LAYER], cnt);
}

// ---- block 3 conv: Cout=2, thread-per-output-pixel, list-driven ----
__global__ void k_conv3(const uint8_t* __restrict__ cnts, const uint8_t* __restrict__ lst,
                        const float* __restrict__ wr, float* __restrict__ z3) {
    __shared__ float sW[9*C2*2];
    for (int i = threadIdx.x; i < 9*C2*2; i += blockDim.x) sW[i] = wr[i];
    __syncthreads();
    int idx = blockIdx.x*blockDim.x + threadIdx.x;
    if (idx >= FRAMES*H3*W3) return;
    int ow = idx % W3;
    int oh = (idx / W3) % H3;
    int tn = idx / (W3*H3);
    int khs[2], ihs[2], nh; int kws[2], iws[2], nw;
    if (oh & 1) { khs[0]=0; ihs[0]=(oh+1)>>1; khs[1]=2; ihs[1]=(oh-1)>>1; nh=2; }
    else        { khs[0]=1; ihs[0]=oh>>1; nh=1; }
    if (ow & 1) { kws[0]=0; iws[0]=(ow+1)>>1; kws[1]=2; iws[1]=(ow-1)>>1; nw=2; }
    else        { kws[0]=1; iws[0]=ow>>1; nw=1; }
    float a0 = 0.f, a1 = 0.f;
    for (int a = 0; a < nh; a++)
        for (int b = 0; b < nw; b++) {
            size_t p = (size_t)tn*(H2*W2) + ihs[a]*W2 + iws[b];
            int cnt = cnts[p];
            const uint8_t* lp = lst + p*32;
            const float* wb = sW + (khs[a]*3 + kws[b])*(C2*2);
            for (int j = 0; j < cnt; j++) {
                int bit = lp[j];
                a0 += wb[bit*2];
                a1 += wb[bit*2+1];
            }
        }
    *(float2*)(z3 + (size_t)idx*2) = make_float2(a0, a1);
}

// ---- final LIF: both channels per thread, writes output [N,C,H,W,T] ----
__global__ void k_lif3out(float* __restrict__ out) {
    const int idx = blockIdx.x*blockDim.x + threadIdx.x;
    if (idx >= NB*H3*W3) return;
    const int pix = idx % (H3*W3);
    const int n   = idx / (H3*W3);
    const size_t base    = ((size_t)n*(H3*W3) + pix)*C3;
    const size_t tstride = (size_t)NB*H3*W3*C3;
    float cur0 = 0.f, vol0 = 0.f, cur1 = 0.f, vol1 = 0.f;
    int cnt = 0;
    float res0[TT], res1[TT];
    #pragma unroll
    for (int t = 0; t < TT; t++) {
        float2 zv = *(const float2*)(g_z3 + (size_t)t*tstride + base);
        cur0 = 0.5f*cur0 + zv.x; vol0 = 0.5f*vol0 + cur0;
        cur1 = 0.5f*cur1 + zv.y; vol1 = 0.5f*vol1 + cur1;
        bool s0 = (vol0 >= 1.0f), s1 = (vol1 >= 1.0f);
        vol0 = s0 ? 0.f : vol0;  vol1 = s1 ? 0.f : vol1;
        res0[t] = s0 ? 1.0f : 0.0f;  res1[t] = s1 ? 1.0f : 0.0f;
        cnt += (s0 ? 1 : 0) + (s1 ? 1 : 0);
    }
    float4* op0 = (float4*)(out + (((size_t)n*C3 + 0)*(H3*W3) + pix)*TT);
    float4* op1 = (float4*)(out + (((size_t)n*C3 + 1)*(H3*W3) + pix)*TT);
    #pragma unroll
    for (int q = 0; q < 8; q++) {
        op0[q] = make_float4(res0[4*q], res0[4*q+1], res0[4*q+2], res0[4*q+3]);
        op1[q] = make_float4(res1[4*q], res1[4*q+1], res1[4*q+2], res1[4*q+3]);
    }
    cnt = __reduce_add_sync(0xffffffffu, cnt);
    if ((threadIdx.x & 31) == 0) atomicAdd(&g_cnt[2], cnt);
}

__global__ void k_final(float* out, int off) {
    if (threadIdx.x == 0) {
        out[off+0] = (float)g_cnt[0] * (1.0f / (float)((size_t)NB*C1*H1*W1*TT));
        out[off+1] = (float)g_cnt[1] * (1.0f / (float)((size_t)NB*C2*H2*W2*TT));
        out[off+2] = (float)g_cnt[2] * (1.0f / (float)((size_t)NB*C3*H3*W3*TT));
    }
}

extern "C" void kernel_launch(void* const* d_in, const int* in_sizes, int n_in,
                              void* d_out, int out_size) {
    const float* x  = (const float*)d_in[0];
    const float* w1 = (const float*)d_in[1];
    const float* w2 = (const float*)d_in[2];
    const float* w3 = (const float*)d_in[3];
    float* out = (float*)d_out;

    void *pc0, *pl0, *pw1, *pw2, *pw3, *pz1, *pc1, *pl1, *pz2, *pc2, *pl2, *pz3;
    cudaGetSymbolAddress(&pc0, g_cnt0);
    cudaGetSymbolAddress(&pl0, g_lst0);
    cudaGetSymbolAddress(&pw1, g_w1r);
    cudaGetSymbolAddress(&pw2, g_w2r);
    cudaGetSymbolAddress(&pw3, g_w3r);
    cudaGetSymbolAddress(&pz1, g_z1);
    cudaGetSymbolAddress(&pc1, g_cnt1);
    cudaGetSymbolAddress(&pl1, g_lst1);
    cudaGetSymbolAddress(&pz2, g_z2);
    cudaGetSymbolAddress(&pc2, g_cnt2);
    cudaGetSymbolAddress(&pl2, g_lst2);
    cudaGetSymbolAddress(&pz3, g_z3);

    // dynamic smem sizes per parity class: NT * CIN * 32 * 4
    const int s1ee = 1*C0*32*4, s1eo = 2*C0*32*4, s1oo = 4*C0*32*4;  // 16K/32K/64K
    const int s2ee = 1*C1*32*4, s2eo = 2*C1*32*4, s2oo = 4*C1*32*4;  // 8K/16K/32K
    cudaFuncSetAttribute((const void*)k_convp<C0,C1,H0,W0,1,1>,
                         cudaFuncAttributeMaxDynamicSharedMemorySize, s1oo);

    // prep
    k_list0<<<(NB*H0*W0*4 + 7)/8, 256>>>(x);
    k_wprep<<<(C0*C1*9 + 255)/256, 256>>>(w1, (float*)pw1, C0, C1);
    k_wprep<<<(C1*C2*9 + 255)/256, 256>>>(w2, (float*)pw2, C1, C2);
    k_wprep<<<(C2*C3*9 + 255)/256, 256>>>(w3, (float*)pw3, C2, C3);

    // block 1: 4 parity conv kernels (cout sliced x2) + LIF
    {
        const uint8_t* c0 = (const uint8_t*)pc0;
        const uint8_t* l0 = (const uint8_t*)pl0;
        const float* w = (const float*)pw1;
        float* z = (float*)pz1;
        k_convp<C0,C1,H0,W0,0,0><<<dim3((FRAMES*16*16+7)/8, 2), 256, s1ee>>>(c0, l0, w, z);
        k_convp<C0,C1,H0,W0,0,1><<<dim3((FRAMES*16*15+7)/8, 2), 256, s1eo>>>(c0, l0, w, z);
        k_convp<C0,C1,H0,W0,1,0><<<dim3((FRAMES*15*16+7)/8, 2), 256, s1eo>>>(c0, l0, w, z);
        k_convp<C0,C1,H0,W0,1,1><<<dim3((FRAMES*15*15+7)/8, 2), 256, s1oo>>>(c0, l0, w, z);
    }
    k_lifB<C1,H0,W0,0><<<(NB*H1*W1*C1)/256, 256>>>(
        (const float*)pz1, (uint8_t*)pc1, (uint8_t*)pl1);

    // block 2
    {
        const uint8_t* c1 = (const uint8_t*)pc1;
        const uint8_t* l1 = (const uint8_t*)pl1;
        const float* w = (const float*)pw2;
        float* z = (float*)pz2;
        k_convp<C1,C2,H1,W1,0,0><<<dim3((FRAMES*31*31+7)/8, 1), 256, s2ee>>>(c1, l1, w, z);
        k_convp<C1,C2,H1,W1,0,1><<<dim3((FRAMES*31*30+7)/8, 1), 256, s2eo>>>(c1, l1, w, z);
        k_convp<C1,C2,H1,W1,1,0><<<dim3((FRAMES*30*31+7)/8, 1), 256, s2eo>>>(c1, l1, w, z);
        k_convp<C1,C2,H1,W1,1,1><<<dim3((FRAMES*30*30+7)/8, 1), 256, s2oo>>>(c1, l1, w, z);
    }
    k_lifB<C2,H1,W1,1><<<(NB*H2*W2*C2 + 255)/256, 256>>>(
        (const float*)pz2, (uint8_t*)pc2, (uint8_t*)pl2);

    // block 3
    k_conv3<<<(FRAMES*H3*W3 + 255)/256, 256>>>(
        (const uint8_t*)pc2, (const uint8_t*)pl2, (const float*)pw3, (float*)pz3);
    k_lif3out<<<(NB*H3*W3 + 255)/256, 256>>>(out);

    k_final<<<1, 32>>>(out, out_size - 3);
}

// round 4
// speedup vs baseline: 1.9058x; 1.9058x over previous
#include <cuda_runtime.h>
#include <stdint.h>

#define TT 32
#define NB 4
#define FRAMES (TT*NB)   // frame index tn = t*NB + n

#define C0 128
#define H0 16
#define W0 16
#define C1 64
#define H1 31
#define W1 31
#define C2 32
#define H2 61
#define W2 61
#define C3 2
#define H3 121
#define W3 121

// ---- device scratch ----
__device__ uint8_t  g_cnt0[FRAMES*H0*W0*4];
__device__ uint8_t  g_lst0[FRAMES*H0*W0*4*32];
__device__ float    g_w1r[9*C0*C1];                    // [tap][ci][co], pre-scaled x2
__device__ float    g_w2r[9*C1*C2];
__device__ float    g_w3r[9*C2*C3];
__device__ float    g_z1[(size_t)FRAMES*H1*W1*C1];
__device__ uint8_t  g_cnt1[FRAMES*H1*W1*2];
__device__ uint8_t  g_lst1[FRAMES*H1*W1*2*32];
__device__ float    g_z2[(size_t)FRAMES*H2*W2*C2];
__device__ uint8_t  g_cnt2[FRAMES*H2*W2];
__device__ uint8_t  g_lst2[(size_t)FRAMES*H2*W2*32];
__device__ float    g_z3[(size_t)FRAMES*H3*W3*C3];
__device__ int      g_cnt[3];

// ---- build layer-0 spike lists from input; zero spike counters ----
__global__ void k_list0(const float* __restrict__ x) {
    const int lane = threadIdx.x & 31;
    const int gw = blockIdx.x*(blockDim.x>>5) + (threadIdx.x>>5);
    if (gw == 0 && lane < 3) g_cnt[lane] = 0;
    const int total = NB*H0*W0*4;
    if (gw >= total) return;
    const int word = gw & 3;
    const int pix  = (gw >> 2) % (H0*W0);
    const int n    = gw / (4*H0*W0);
    const int ci = word*32 + lane;
    const float4* xp = (const float4*)(x + (((size_t)n*C0 + ci)*(H0*W0) + pix)*TT);
    float4 v[8];
    #pragma unroll
    for (int q = 0; q < 8; q++) v[q] = xp[q];
    const uint32_t ltmask = (1u << lane) - 1u;
    #pragma unroll
    for (int t = 0; t < TT; t++) {
        float4 vv = v[t >> 2];
        float f = (t&3)==0 ? vv.x : (t&3)==1 ? vv.y : (t&3)==2 ? vv.z : vv.w;
        bool s = (f >= 0.5f);
        uint32_t bal = __ballot_sync(0xffffffffu, s);
        size_t li = ((size_t)(t*NB+n)*(H0*W0) + pix)*4 + word;
        if (s) g_lst0[li*32 + __popc(bal & ltmask)] = (uint8_t)lane;
        if (lane == 0) g_cnt0[li] = (uint8_t)__popc(bal);
    }
}

// ---- rearrange weights: wr[tap][ci][co] = 2 * w[ci][co][tap] ----
__global__ void k_wprep(const float* __restrict__ w, float* __restrict__ wr,
                        int cin, int cout) {
    int idx = blockIdx.x*blockDim.x + threadIdx.x;
    int total = cin*cout*9;
    if (idx >= total) return;
    int tap = idx % 9;
    int rest = idx/9;
    int co = rest % cout;
    int ci = rest / cout;
    wr[(tap*cin + ci)*cout + co] = 2.0f * w[(ci*cout + co)*9 + tap];
}

// ---- parity-specialized sparse transposed conv (persistent, list-driven) ----
// One warp = one output pixel, all COUT couts (VEC = COUT/32 per lane).
// Order per cout: kh asc, kw asc, ci asc — single running accumulator.
template<int CIN, int COUT, int HIN, int WIN, int PH, int PW>
__global__ void __launch_bounds__(1024)
k_convp(const uint8_t* __restrict__ cnts, const uint8_t* __restrict__ lst,
        const float* __restrict__ wr, float* __restrict__ zOut) {
    constexpr int WORDS = CIN/32;
    constexpr int VEC = COUT/32;
    constexpr int HOUT = 2*HIN-1, WOUT = 2*WIN-1;
    constexpr int ROWS = PH ? HIN-1 : HIN;
    constexpr int COLS = PW ? WIN-1 : WIN;
    constexpr int NKH = PH ? 2 : 1;
    constexpr int NKW = PW ? 2 : 1;
    constexpr int NT = NKH*NKW;
    extern __shared__ float sW[];    // [NT][CIN][COUT]
    for (int i = threadIdx.x; i < NT*CIN*COUT; i += blockDim.x) {
        int ti = i / (CIN*COUT);
        int r  = i - ti*(CIN*COUT);
        int kh = PH ? (ti/NKW)*2 : 1;
        int kw = PW ? (ti%NKW)*2 : 1;
        sW[i] = wr[(kh*3+kw)*(CIN*COUT) + r];
    }
    __syncthreads();
    const int lane = threadIdx.x & 31;
    const int warp = threadIdx.x >> 5;
    const int wpb  = blockDim.x >> 5;
    const int total = FRAMES*ROWS*COLS;
    for (int task = blockIdx.x*wpb + warp; task < total; task += gridDim.x*wpb) {
        const int ocol = task % COLS;
        const int orow = (task / COLS) % ROWS;
        const int tn   = task / (COLS*ROWS);
        float acc0 = 0.f, acc1 = 0.f;
        #pragma unroll
        for (int th = 0; th < NKH; th++) {
            const int ih = PH ? (th == 0 ? orow+1 : orow) : orow;
            #pragma unroll
            for (int tw = 0; tw < NKW; tw++) {
                const int iw = PW ? (tw == 0 ? ocol+1 : ocol) : ocol;
                const int ti = th*NKW + tw;
                const size_t pbase = ((size_t)tn*(HIN*WIN) + ih*WIN + iw)*WORDS;
                #pragma unroll
                for (int wo = 0; wo < WORDS; wo++) {
                    const int cnt = cnts[pbase + wo];
                    const uint8_t* lp = lst + (pbase + wo)*32;
                    const float* wb = sW + (ti*CIN + wo*32)*COUT + lane*VEC;
                    int j = 0;
                    for (; j + 4 <= cnt; j += 4) {
                        uint32_t q = *(const uint32_t*)(lp + j);
                        if (VEC == 2) {
                            float2 a = *(const float2*)(wb + ((q      ) & 0xFF)*COUT);
                            float2 b = *(const float2*)(wb + ((q >>  8) & 0xFF)*COUT);
                            float2 c = *(const float2*)(wb + ((q >> 16) & 0xFF)*COUT);
                            float2 d = *(const float2*)(wb + ((q >> 24)       )*COUT);
                            acc0 += a.x; acc1 += a.y;
                            acc0 += b.x; acc1 += b.y;
                            acc0 += c.x; acc1 += c.y;
                            acc0 += d.x; acc1 += d.y;
                        } else {
                            acc0 += wb[((q      ) & 0xFF)*COUT];
                            acc0 += wb[((q >>  8) & 0xFF)*COUT];
                            acc0 += wb[((q >> 16) & 0xFF)*COUT];
                            acc0 += wb[((q >> 24)       )*COUT];
                        }
                    }
                    for (; j < cnt; j++) {
                        if (VEC == 2) {
                            float2 a = *(const float2*)(wb + lp[j]*COUT);
                            acc0 += a.x; acc1 += a.y;
                        } else {
                            acc0 += wb[lp[j]*COUT];
                        }
                    }
                }
            }
        }
        const int oh = PH ? 2*orow+1 : 2*orow;
        const int ow = PW ? 2*ocol+1 : 2*ocol;
        float* zp = zOut + (((size_t)tn*HOUT + oh)*WOUT + ow)*COUT;
        if (VEC == 2) *(float2*)(zp + lane*2) = make_float2(acc0, acc1);
        else          zp[lane] = acc0;
    }
}

// ---- CUBA LIF scan; emits next-layer spike lists + counts + spike total ----
template<int C, int HIN, int WIN, int LAYER>
__global__ void k_lifB(const float* __restrict__ z, uint8_t* __restrict__ cnts,
                       uint8_t* __restrict__ lst) {
    constexpr int HOUT = 2*HIN-1, WOUT = 2*WIN-1, POUT = HOUT*WOUT;
    const int idx = blockIdx.x*blockDim.x + threadIdx.x;
    const int total = NB*POUT*C;    // divisible by 32 -> warps fully in/out
    if (idx >= total) return;
    const int c   = idx % C;
    const int pix = (idx / C) % POUT;
    const int n   = idx / (C*POUT);
    const int lane = threadIdx.x & 31;
    const int word = c >> 5;
    const size_t zbase    = ((size_t)n*POUT + pix)*C + c;
    const size_t ztstride = (size_t)NB*POUT*C;
    const size_t lbase    = ((size_t)n*POUT + pix)*(C/32) + word;
    const size_t lstride  = (size_t)NB*POUT*(C/32);
    const uint32_t ltmask = (1u << lane) - 1u;
    float cur = 0.f, vol = 0.f;
    int cnt = 0;
    #pragma unroll
    for (int t = 0; t < TT; t++) {
        float zv = z[(size_t)t*ztstride + zbase];
        cur = 0.5f*cur + zv;
        vol = 0.5f*vol + cur;
        bool s = (vol >= 1.0f);
        vol = s ? 0.f : vol;
        cnt += s ? 1 : 0;
        uint32_t bal = __ballot_sync(0xffffffffu, s);
        size_t li = (size_t)t*lstride + lbase;
        if (s) lst[li*32 + __popc(bal & ltmask)] = (uint8_t)lane;
        if (lane == 0) cnts[li] = (uint8_t)__popc(bal);
    }
    cnt = __reduce_add_sync(0xffffffffu, cnt);
    if (lane == 0) atomicAdd(&g_cnt[LAYER], cnt);
}

// ---- block 3 conv: Cout=2, thread-per-output-pixel, list-driven ----
__global__ void k_conv3(const uint8_t* __restrict__ cnts, const uint8_t* __restrict__ lst,
                        const float* __restrict__ wr, float* __restrict__ z3) {
    __shared__ float sW[9*C2*2];
    for (int i = threadIdx.x; i < 9*C2*2; i += blockDim.x) sW[i] = wr[i];
    __syncthreads();
    int idx = blockIdx.x*blockDim.x + threadIdx.x;
    if (idx >= FRAMES*H3*W3) return;
    int ow = idx % W3;
    int oh = (idx / W3) % H3;
    int tn = idx / (W3*H3);
    int khs[2], ihs[2], nh; int kws[2], iws[2], nw;
    if (oh & 1) { khs[0]=0; ihs[0]=(oh+1)>>1; khs[1]=2; ihs[1]=(oh-1)>>1; nh=2; }
    else        { khs[0]=1; ihs[0]=oh>>1; nh=1; }
    if (ow & 1) { kws[0]=0; iws[0]=(ow+1)>>1; kws[1]=2; iws[1]=(ow-1)>>1; nw=2; }
    else        { kws[0]=1; iws[0]=ow>>1; nw=1; }
    float a0 = 0.f, a1 = 0.f;
    for (int a = 0; a < nh; a++)
        for (int b = 0; b < nw; b++) {
            size_t p = (size_t)tn*(H2*W2) + ihs[a]*W2 + iws[b];
            int cnt = cnts[p];
            const uint8_t* lp = lst + p*32;
            const float* wb = sW + (khs[a]*3 + kws[b])*(C2*2);
            for (int j = 0; j < cnt; j++) {
                int bit = lp[j];
                a0 += wb[bit*2];
                a1 += wb[bit*2+1];
            }
        }
    *(float2*)(z3 + (size_t)idx*2) = make_float2(a0, a1);
}

// ---- final LIF: both channels per thread, writes output [N,C,H,W,T] ----
__global__ void k_lif3out(float* __restrict__ out) {
    const int idx = blockIdx.x*blockDim.x + threadIdx.x;
    if (idx >= NB*H3*W3) return;
    const int pix = idx % (H3*W3);
    const int n   = idx / (H3*W3);
    const size_t base    = ((size_t)n*(H3*W3) + pix)*C3;
    const size_t tstride = (size_t)NB*H3*W3*C3;
    float cur0 = 0.f, vol0 = 0.f, cur1 = 0.f, vol1 = 0.f;
    int cnt = 0;
    float res0[TT], res1[TT];
    #pragma unroll
    for (int t = 0; t < TT; t++) {
        float2 zv = *(const float2*)(g_z3 + (size_t)t*tstride + base);
        cur0 = 0.5f*cur0 + zv.x; vol0 = 0.5f*vol0 + cur0;
        cur1 = 0.5f*cur1 + zv.y; vol1 = 0.5f*vol1 + cur1;
        bool s0 = (vol0 >= 1.0f), s1 = (vol1 >= 1.0f);
        vol0 = s0 ? 0.f : vol0;  vol1 = s1 ? 0.f : vol1;
        res0[t] = s0 ? 1.0f : 0.0f;  res1[t] = s1 ? 1.0f : 0.0f;
        cnt += (s0 ? 1 : 0) + (s1 ? 1 : 0);
    }
    float4* op0 = (float4*)(out + (((size_t)n*C3 + 0)*(H3*W3) + pix)*TT);
    float4* op1 = (float4*)(out + (((size_t)n*C3 + 1)*(H3*W3) + pix)*TT);
    #pragma unroll
    for (int q = 0; q < 8; q++) {
        op0[q] = make_float4(res0[4*q], res0[4*q+1], res0[4*q+2], res0[4*q+3]);
        op1[q] = make_float4(res1[4*q], res1[4*q+1], res1[4*q+2], res1[4*q+3]);
    }
    cnt = __reduce_add_sync(0xffffffffu, cnt);
    if ((threadIdx.x & 31) == 0) atomicAdd(&g_cnt[2], cnt);
}

__global__ void k_final(float* out, int off) {
    if (threadIdx.x == 0) {
        out[off+0] = (float)g_cnt[0] * (1.0f / (float)((size_t)NB*C1*H1*W1*TT));
        out[off+1] = (float)g_cnt[1] * (1.0f / (float)((size_t)NB*C2*H2*W2*TT));
        out[off+2] = (float)g_cnt[2] * (1.0f / (float)((size_t)NB*C3*H3*W3*TT));
    }
}

extern "C" void kernel_launch(void* const* d_in, const int* in_sizes, int n_in,
                              void* d_out, int out_size) {
    const float* x  = (const float*)d_in[0];
    const float* w1 = (const float*)d_in[1];
    const float* w2 = (const float*)d_in[2];
    const float* w3 = (const float*)d_in[3];
    float* out = (float*)d_out;

    void *pc0, *pl0, *pw1, *pw2, *pw3, *pz1, *pc1, *pl1, *pz2, *pc2, *pl2, *pz3;
    cudaGetSymbolAddress(&pc0, g_cnt0);
    cudaGetSymbolAddress(&pl0, g_lst0);
    cudaGetSymbolAddress(&pw1, g_w1r);
    cudaGetSymbolAddress(&pw2, g_w2r);
    cudaGetSymbolAddress(&pw3, g_w3r);
    cudaGetSymbolAddress(&pz1, g_z1);
    cudaGetSymbolAddress(&pc1, g_cnt1);
    cudaGetSymbolAddress(&pl1, g_lst1);
    cudaGetSymbolAddress(&pz2, g_z2);
    cudaGetSymbolAddress(&pc2, g_cnt2);
    cudaGetSymbolAddress(&pl2, g_lst2);
    cudaGetSymbolAddress(&pz3, g_z3);

    // dynamic smem: NT * CIN * COUT * 4 bytes
    const int s1ee = 1*C0*C1*4, s1eo = 2*C0*C1*4, s1oo = 4*C0*C1*4;  // 32K/64K/128K
    const int s2ee = 1*C1*C2*4, s2eo = 2*C1*C2*4, s2oo = 4*C1*C2*4;  // 8K/16K/32K
    cudaFuncSetAttribute((const void*)k_convp<C0,C1,H0,W0,0,1>,
                         cudaFuncAttributeMaxDynamicSharedMemorySize, s1eo);
    cudaFuncSetAttribute((const void*)k_convp<C0,C1,H0,W0,1,0>,
                         cudaFuncAttributeMaxDynamicSharedMemorySize, s1eo);
    cudaFuncSetAttribute((const void*)k_convp<C0,C1,H0,W0,1,1>,
                         cudaFuncAttributeMaxDynamicSharedMemorySize, s1oo);

    // prep
    k_list0<<<(NB*H0*W0*4 + 7)/8, 256>>>(x);
    k_wprep<<<(C0*C1*9 + 255)/256, 256>>>(w1, (float*)pw1, C0, C1);
    k_wprep<<<(C1*C2*9 + 255)/256, 256>>>(w2, (float*)pw2, C1, C2);
    k_wprep<<<(C2*C3*9 + 255)/256, 256>>>(w3, (float*)pw3, C2, C3);

    // block 1: 4 persistent parity conv kernels + LIF
    {
        const uint8_t* c0 = (const uint8_t*)pc0;
        const uint8_t* l0 = (const uint8_t*)pl0;
        const float* w = (const float*)pw1;
        float* z = (float*)pz1;
        k_convp<C0,C1,H0,W0,0,0><<<296, 1024, s1ee>>>(c0, l0, w, z);
        k_convp<C0,C1,H0,W0,0,1><<<296, 1024, s1eo>>>(c0, l0, w, z);
        k_convp<C0,C1,H0,W0,1,0><<<296, 1024, s1eo>>>(c0, l0, w, z);
        k_convp<C0,C1,H0,W0,1,1><<<148, 1024, s1oo>>>(c0, l0, w, z);
    }
    k_lifB<C1,H0,W0,0><<<(NB*H1*W1*C1)/256, 256>>>(
        (const float*)pz1, (uint8_t*)pc1, (uint8_t*)pl1);

    // block 2
    {
        const uint8_t* c1 = (const uint8_t*)pc1;
        const uint8_t* l1 = (const uint8_t*)pl1;
        const float* w = (const float*)pw2;
        float* z = (float*)pz2;
        k_convp<C1,C2,H1,W1,0,0><<<296, 1024, s2ee>>>(c1, l1, w, z);
        k_convp<C1,C2,H1,W1,0,1><<<296, 1024, s2eo>>>(c1, l1, w, z);
        k_convp<C1,C2,H1,W1,1,0><<<296, 1024, s2eo>>>(c1, l1, w, z);
        k_convp<C1,C2,H1,W1,1,1><<<296, 1024, s2oo>>>(c1, l1, w, z);
    }
    k_lifB<C2,H1,W1,1><<<(NB*H2*W2*C2 + 255)/256, 256>>>(
        (const float*)pz2, (uint8_t*)pc2, (uint8_t*)pl2);

    // block 3
    k_conv3<<<(FRAMES*H3*W3 + 255)/256, 256>>>(
        (const uint8_t*)pc2, (const uint8_t*)pl2, (const float*)pw3, (float*)pz3);
    k_lif3out<<<(NB*H3*W3 + 255)/256, 256>>>(out);

    k_final<<<1, 32>>>(out, out_size - 3);
}